// round 16
// baseline (speedup 1.0000x reference)
#include <cuda_runtime.h>
#include <cuda_fp16.h>
#include <math.h>
#include <stdint.h>

#define LSEQ 2048
#define DM   1024
#define DI   2048
#define DS   16
#define DTR  64
#define DBLC 96   /* DTR + 2*DS */
#define XP_SPLITS 8

// ======================= static scratch (no allocation) ======================
__device__ float g_x  [LSEQ * DM];        // residual stream (fp32)
__device__ float g_dbl[LSEQ * DBLC];      // x_proj out (fp32: feeds scan B/C)
__device__ float g_dblp[XP_SPLITS * LSEQ * DBLC]; // split-K partials
__device__ float g_dt [LSEQ * DI];        // softplus(dt_proj) (fp32: compounds)

// fp16 activation buffers
__device__ __align__(16) __half g_h_h  [LSEQ * DM];     // post-LN
__device__ __align__(16) __half g_xz   [LSEQ * 2 * DI]; // in_proj out [xc | z]
__device__ __align__(16) __half g_xc_h [LSEQ * DI];     // conv+silu out
__device__ __align__(16) __half g_y_h  [LSEQ * DI];     // scan out
__device__ __align__(16) __half g_da_h [LSEQ * DTR];    // dt_lr

// fp16 weights: hi for all; lo only for x_proj/dt_proj (2-pass, exact-B)
__device__ __align__(16) __half g_inw_h[2 * 2 * DI * DM];
__device__ __align__(16) __half g_xpw_h[2 * DBLC * DI];
__device__ __align__(16) __half g_xpw_l[2 * DBLC * DI];
__device__ __align__(16) __half g_dtw_h[2 * DI * DTR];
__device__ __align__(16) __half g_dtw_l[2 * DI * DTR];
__device__ __align__(16) __half g_otw_h[2 * DM * DI];

// ======================= helpers =============================================
__device__ __forceinline__ float siluf(float x) { return x / (1.0f + __expf(-x)); }
__device__ __forceinline__ float softplusf(float x) {
    if (x > 20.0f) return x;
    return log1pf(__expf(x));
}
__device__ __forceinline__ void split_fp16(float v, __half& h, __half& l) {
    h = __float2half(v);
    l = __float2half(v - __half2float(h));
}
__device__ __forceinline__ uint32_t smem_u32(const void* p) {
    uint32_t a;
    asm("{ .reg .u64 t; cvta.to.shared.u64 t, %1; cvt.u32.u64 %0, t; }" : "=r"(a) : "l"(p));
    return a;
}

__device__ __forceinline__ void cpa16(uint32_t d, const void* s, int sz) {
    asm volatile("cp.async.cg.shared.global [%0], [%1], 16, %2;" :: "r"(d), "l"(s), "r"(sz) : "memory");
}
__device__ __forceinline__ void cpa16f(uint32_t d, const void* s) {
    asm volatile("cp.async.cg.shared.global [%0], [%1], 16;" :: "r"(d), "l"(s) : "memory");
}
#define CP_COMMIT() asm volatile("cp.async.commit_group;" ::: "memory")
#define CP_WAIT(n)  asm volatile("cp.async.wait_group %0;" :: "n"(n) : "memory")

#define LDSM4(r0, r1, r2, r3, addr)                                            \
    asm volatile("ldmatrix.sync.aligned.m8n8.x4.shared.b16 {%0,%1,%2,%3}, [%4];" \
        : "=r"(r0), "=r"(r1), "=r"(r2), "=r"(r3) : "r"(addr))

#define MMA16816(d, a, b)                                                      \
    asm volatile("mma.sync.aligned.m16n8k16.row.col.f32.f16.f16.f32 "          \
        "{%0,%1,%2,%3},{%4,%5,%6,%7},{%8,%9},{%0,%1,%2,%3};"                   \
        : "+f"((d)[0]), "+f"((d)[1]), "+f"((d)[2]), "+f"((d)[3])               \
        : "r"((a)[0]), "r"((a)[1]), "r"((a)[2]), "r"((a)[3]),                  \
          "r"((b)[0]), "r"((b)[1]))

// ======================= HMMA GEMM ===========================================
// C[m,n] = sum_k A[m,k]*B[n,k], fp16. BK=64 (128B rows, slot^=(r&7) swizzle).
// NPASS=1: acc += Ah*Bh — 24KB stage, 3-stage ring, single sync/iter.
// NPASS=2: + Ah*Bl (exact-B) — 40KB stage, 2-stage ring (R14-proven ordering:
//   end-of-iter-s loads stage s+1 into buf (s+1)&1; top-of-iter CP_WAIT(0)).
// BM=64, BN=128, 128 threads, 4 warps (2m x 2n), warp tile 32x64.
// Occupancy kept in proven 2-4 CTAs/SM window (R12/R13 A/B).
// EPI 0: store; 1: softplus(+bias); 2: acc + res residual.
// OH 1: C is __half (half2 stores); OH 0: C is fp32 (float2 stores).
// Split-K via blockIdx.z (stores to C + z*czoff).

#define OFF_B   8192
#define OFF_BLO 24576

template<int NPASS>
__device__ __forceinline__ void stage_load(
    uint32_t sbase,
    const __half* __restrict__ Ah,
    const __half* __restrict__ Bh, const __half* __restrict__ Bl,
    int m0, int n0, int k0, int K, int Nmat, int tid)
{
    // A: 64 rows x 128B
    #pragma unroll
    for (int it = 0; it < 4; it++) {
        int id   = tid + it * 128;       // 0..511
        int r    = id >> 3;              // 0..63
        int slot = id & 7;
        uint32_t so = (uint32_t)(r * 128 + ((slot ^ (r & 7)) << 4));
        size_t ga = (size_t)(m0 + r) * K + k0 + slot * 8;
        cpa16(sbase + so, Ah + ga, 16);
    }
    // B: 128 rows x 128B (hi; lo only for NPASS==2)
    #pragma unroll
    for (int it = 0; it < 8; it++) {
        int id   = tid + it * 128;       // 0..1023
        int r    = id >> 3;              // 0..127
        int slot = id & 7;
        uint32_t so = (uint32_t)(r * 128 + ((slot ^ (r & 7)) << 4));
        int nrow = n0 + r;
        bool ok  = nrow < Nmat;
        size_t gb = (size_t)(ok ? nrow : 0) * K + k0 + slot * 8;
        cpa16(sbase + OFF_B + so, Bh + gb, ok ? 16 : 0);
        if (NPASS == 2) cpa16(sbase + OFF_BLO + so, Bl + gb, ok ? 16 : 0);
    }
}

template<int EPI, int NPASS, int OH>
__global__ void __launch_bounds__(128) gemm_mma(
    const __half* __restrict__ Ah,
    const __half* __restrict__ Bh, const __half* __restrict__ Bl,
    void* __restrict__ Cv, const float* __restrict__ res,
    int ldc, int Nmat, int K, int Kslice,
    const float* __restrict__ bias, int czoff)
{
    constexpr int SS = (NPASS == 1) ? 24576 : 40960;  // stage bytes
    constexpr int NS = (NPASS == 1) ? 3 : 2;          // ring depth

    extern __shared__ char smem[];
    const uint32_t sb = smem_u32(smem);
    const int tid  = threadIdx.x;
    const int lane = tid & 31;
    const int wid  = tid >> 5;
    const int m0   = blockIdx.y * 64;
    const int n0   = blockIdx.x * 128;
    const int kbase = blockIdx.z * Kslice;
    const int wm   = (wid & 1) * 32;    // warp m offset in tile
    const int wn   = (wid >> 1) * 64;   // warp n offset in tile

    // precompute ldmatrix lane offsets (ks=0); ks toggles ^(ks<<5)
    uint32_t aoff[2], boff[4];
    {
        int mat = lane >> 3, row = lane & 7;
        #pragma unroll
        for (int mf = 0; mf < 2; mf++) {
            int r = wm + mf * 16 + ((mat & 1) << 3) + row;
            int slot0 = mat >> 1;
            aoff[mf] = (uint32_t)(r * 128 + ((slot0 ^ (r & 7)) << 4));
        }
        #pragma unroll
        for (int p = 0; p < 4; p++) {
            int n = wn + p * 16 + ((mat >> 1) << 3) + row;
            int slot0 = mat & 1;
            boff[p] = (uint32_t)(n * 128 + ((slot0 ^ (n & 7)) << 4));
        }
    }

    float acc[2][8][4];
    #pragma unroll
    for (int i = 0; i < 2; i++)
        #pragma unroll
        for (int j = 0; j < 8; j++)
            #pragma unroll
            for (int q = 0; q < 4; q++) acc[i][j][q] = 0.f;

    const int nsteps = Kslice >> 6;

    if (NS == 3) {
        // prologue: prefetch 2 stages
        const int pre = (2 < nsteps) ? 2 : nsteps;
        for (int t = 0; t < pre; t++) {
            stage_load<NPASS>(sb + t * SS, Ah, Bh, Bl,
                              m0, n0, kbase + (t << 6), K, Nmat, tid);
            CP_COMMIT();
        }
    } else {
        stage_load<NPASS>(sb, Ah, Bh, Bl, m0, n0, kbase, K, Nmat, tid);
        CP_COMMIT();
    }

    for (int s = 0; s < nsteps; s++) {
        if (NS == 3) {
            if (s + 2 < nsteps) CP_WAIT(1);
            else                CP_WAIT(0);
            __syncthreads();
            // single-sync path: issue load for s+2 AFTER the barrier
            if (s + 2 < nsteps) {
                stage_load<NPASS>(sb + ((s + 2) % 3) * SS, Ah, Bh, Bl,
                                  m0, n0, kbase + ((s + 2) << 6), K, Nmat, tid);
                CP_COMMIT();
            }
        } else {
            CP_WAIT(0);
            __syncthreads();
        }

        const uint32_t base = sb + (s % NS) * SS;
        #pragma unroll
        for (int ks = 0; ks < 4; ks++) {
            const uint32_t kx = (uint32_t)ks << 5;
            uint32_t ah[2][4], bh[8][2], bl[8][2];
            #pragma unroll
            for (int mf = 0; mf < 2; mf++)
                LDSM4(ah[mf][0], ah[mf][1], ah[mf][2], ah[mf][3], base + (aoff[mf] ^ kx));
            #pragma unroll
            for (int p = 0; p < 4; p++) {
                LDSM4(bh[2*p][0], bh[2*p][1], bh[2*p+1][0], bh[2*p+1][1],
                      base + OFF_B + (boff[p] ^ kx));
                if (NPASS == 2)
                    LDSM4(bl[2*p][0], bl[2*p][1], bl[2*p+1][0], bl[2*p+1][1],
                          base + OFF_BLO + (boff[p] ^ kx));
            }
            #pragma unroll
            for (int mf = 0; mf < 2; mf++)
                #pragma unroll
                for (int nf = 0; nf < 8; nf++)
                    MMA16816(acc[mf][nf], ah[mf], bh[nf]);
            if (NPASS == 2) {
                #pragma unroll
                for (int mf = 0; mf < 2; mf++)
                    #pragma unroll
                    for (int nf = 0; nf < 8; nf++)
                        MMA16816(acc[mf][nf], ah[mf], bl[nf]);
            }
        }

        if (NS == 2) {
            // R14-proven ordering: barrier then load stage s+1 into buf (s+1)&1
            __syncthreads();
            if (s + 1 < nsteps) {
                stage_load<NPASS>(sb + ((s + 1) & 1) * SS, Ah, Bh, Bl,
                                  m0, n0, kbase + ((s + 1) << 6), K, Nmat, tid);
                CP_COMMIT();
            }
        }
    }

    // ---------------- epilogue ----------------
    const int mrow = m0 + wm + (lane >> 2);
    const int ncol = n0 + wn + (lane & 3) * 2;   // even; pairs (n, n+1)
    #pragma unroll
    for (int mf = 0; mf < 2; mf++) {
        #pragma unroll
        for (int nf = 0; nf < 8; nf++) {
            const int n = ncol + nf * 8;
            if (n < Nmat) {
                #pragma unroll
                for (int half = 0; half < 2; half++) {
                    const int m = mrow + mf * 16 + half * 8;
                    float2 v = make_float2(acc[mf][nf][half * 2 + 0],
                                           acc[mf][nf][half * 2 + 1]);
                    if (EPI == 1) {
                        v.x = softplusf(v.x + bias[n]);
                        v.y = softplusf(v.y + bias[n + 1]);
                    }
                    if (EPI == 2) {
                        float2 r = *(const float2*)(res + (size_t)m * ldc + n);
                        v.x += r.x; v.y += r.y;
                    }
                    if (OH) {
                        __half* Cz = (__half*)Cv + (size_t)blockIdx.z * czoff;
                        *(__half2*)(Cz + (size_t)m * ldc + n) =
                            __floats2half2_rn(v.x, v.y);
                    } else {
                        float* Cz = (float*)Cv + (size_t)blockIdx.z * czoff;
                        *(float2*)(Cz + (size_t)m * ldc + n) = v;
                    }
                }
            }
        }
    }
}

// reduce split-K partials + extract dt_lr fp16 in one pass
__global__ void reduce_dbl_kernel(const float* __restrict__ p, float* __restrict__ d,
                                  __half* __restrict__ dah) {
    int i = blockIdx.x * blockDim.x + threadIdx.x;
    if (i >= LSEQ * DBLC) return;
    float s = 0.f;
    #pragma unroll
    for (int z = 0; z < XP_SPLITS; z++) s += p[z * LSEQ * DBLC + i];
    d[i] = s;
    int row = i / DBLC, c = i - row * DBLC;
    if (c < DTR) dah[row * DTR + c] = __float2half(s);
}

// ======================= misc kernels ========================================
__global__ void convert_split_kernel(const float* __restrict__ s,
                                     __half* __restrict__ h,
                                     __half* __restrict__ l, int n) {
    int i = blockIdx.x * blockDim.x + threadIdx.x;
    if (i < n) { __half hv, lv; split_fp16(s[i], hv, lv); h[i] = hv; l[i] = lv; }
}

__global__ void convert_h_kernel(const float* __restrict__ s,
                                 __half* __restrict__ h, int n) {
    int i = blockIdx.x * blockDim.x + threadIdx.x;
    if (i < n) h[i] = __float2half(s[i]);
}

// layernorm -> fp16 hi (BF=1) or fp32 (BF=0)
template<int BF>
__global__ void __launch_bounds__(256) ln_kernel(
    const float* __restrict__ x, const float* __restrict__ w, const float* __restrict__ b,
    float* __restrict__ outf, __half* __restrict__ oh)
{
    int row = blockIdx.x, t = threadIdx.x;
    const float* xr = x + row * DM;
    float4 v = *(const float4*)(xr + t * 4);
    float s  = v.x + v.y + v.z + v.w;
    float ss = v.x * v.x + v.y * v.y + v.z * v.z + v.w * v.w;
    #pragma unroll
    for (int o = 16; o; o >>= 1) {
        s  += __shfl_xor_sync(0xffffffffu, s,  o);
        ss += __shfl_xor_sync(0xffffffffu, ss, o);
    }
    __shared__ float sr[8], sq[8], smu, srs;
    int wid = t >> 5, lane = t & 31;
    if (lane == 0) { sr[wid] = s; sq[wid] = ss; }
    __syncthreads();
    if (t == 0) {
        float S = 0.f, SS = 0.f;
        #pragma unroll
        for (int i = 0; i < 8; i++) { S += sr[i]; SS += sq[i]; }
        float mu = S * (1.0f / DM);
        smu = mu; srs = rsqrtf(SS * (1.0f / DM) - mu * mu + 1e-5f);
    }
    __syncthreads();
    float mu = smu, rs = srs;
    float4 wv = *(const float4*)(w + t * 4);
    float4 bv = *(const float4*)(b + t * 4);
    float o0 = (v.x - mu) * rs * wv.x + bv.x;
    float o1 = (v.y - mu) * rs * wv.y + bv.y;
    float o2 = (v.z - mu) * rs * wv.z + bv.z;
    float o3 = (v.w - mu) * rs * wv.w + bv.w;
    size_t base = (size_t)row * DM + t * 4;
    if (BF) {
        oh[base + 0] = __float2half(o0);
        oh[base + 1] = __float2half(o1);
        oh[base + 2] = __float2half(o2);
        oh[base + 3] = __float2half(o3);
    } else {
        float4 o4; o4.x = o0; o4.y = o1; o4.z = o2; o4.w = o3;
        *(float4*)(outf + base) = o4;
    }
}

// causal depthwise conv(k=4) + silu; fp16 in (xz), fp16 out (xc)
__global__ void conv_silu_kernel(const __half* __restrict__ xz,
                                 const float* __restrict__ cw, const float* __restrict__ cb,
                                 __half* __restrict__ xch)
{
    int idx = blockIdx.x * blockDim.x + threadIdx.x;
    if (idx >= LSEQ * DI) return;
    int l = idx / DI, e = idx - l * DI;
    float acc = cb[e];
    #pragma unroll
    for (int k = 0; k < 4; k++) {
        int ls = l + k - 3;
        if (ls >= 0)
            acc = fmaf(__half2float(xz[(size_t)ls * (2 * DI) + e]), cw[e * 4 + k], acc);
    }
    xch[idx] = __float2half(siluf(acc));
}

// ======= selective scan: smem-staged, cp.async double-buffered ===============
// dt fp32; xc/z fp16; B/C fp32 from dbl.
#define STT 64
#define NCHUNK (LSEQ / STT)

__global__ void __launch_bounds__(256) scan_kernel(
    const float* __restrict__ dbl, const float* __restrict__ dtf,
    const __half* __restrict__ xzh, const __half* __restrict__ xch,
    const float* __restrict__ A_log, const float* __restrict__ Dp,
    __half* __restrict__ yh)
{
    __shared__ float  sdt[2][STT][16];
    __shared__ __half sxc[2][STT][16];
    __shared__ __half sz [2][STT][16];
    __shared__ float  sbc[2][STT][32];

    const int t  = threadIdx.x;
    const int n  = t & 15;          // state index
    const int cj = t >> 4;          // channel-in-block 0..15
    const int e0 = blockIdx.x * 16;
    const int e  = e0 + cj;

    const uint32_t a_dt = smem_u32(&sdt[0][0][0]);
    const uint32_t a_xc = smem_u32(&sxc[0][0][0]);
    const uint32_t a_z  = smem_u32(&sz [0][0][0]);
    const uint32_t a_bc = smem_u32(&sbc[0][0][0]);

    const float Aen = -__expf(A_log[e * DS + n]);
    const float Dv  = Dp[e];
    float h = 0.f;

    const int lr  = t >> 2, ls = t & 3;
    const int hr  = (t & 127) >> 1, hs = t & 1;
    const int br  = t >> 3, bs = t & 7;

    auto load_chunk = [&](int c, int buf) {
        const int l0 = c * STT;
        const uint32_t bo_dt = (uint32_t)buf * (STT * 16 * 4);
        const uint32_t bo_h  = (uint32_t)buf * (STT * 16 * 2);
        const uint32_t bo_bc = (uint32_t)buf * (STT * 32 * 4);
        cpa16f(a_dt + bo_dt + (uint32_t)(lr * 64 + ls * 16),
               dtf + (size_t)(l0 + lr) * DI + e0 + ls * 4);
        if (t < 128) {
            cpa16f(a_xc + bo_h + (uint32_t)(hr * 32 + hs * 16),
                   xch + (size_t)(l0 + hr) * DI + e0 + hs * 8);
        } else {
            cpa16f(a_z + bo_h + (uint32_t)(hr * 32 + hs * 16),
                   xzh + (size_t)(l0 + hr) * (2 * DI) + DI + e0 + hs * 8);
        }
        #pragma unroll
        for (int it = 0; it < 2; it++) {
            int row = br + it * 32;
            cpa16f(a_bc + bo_bc + (uint32_t)(row * 128 + bs * 16),
                   dbl + (size_t)(l0 + row) * DBLC + DTR + bs * 4);
        }
    };

    load_chunk(0, 0);
    CP_COMMIT();

    for (int c = 0; c < NCHUNK; c++) {
        if (c + 1 < NCHUNK) {
            load_chunk(c + 1, (c + 1) & 1);
            CP_COMMIT();
            CP_WAIT(1);
        } else {
            CP_WAIT(0);
        }
        __syncthreads();

        const int buf = c & 1;
        const int lbase = c * STT;
        #pragma unroll 8
        for (int s = 0; s < STT; s++) {
            float dt  = sdt[buf][s][cj];
            float xcv = __half2float(sxc[buf][s][cj]);
            float Bv  = sbc[buf][s][n];
            float Cv  = sbc[buf][s][16 + n];
            float dA  = __expf(dt * Aen);
            h = fmaf(dA, h, dt * xcv * Bv);
            float p = h * Cv;
            p += __shfl_xor_sync(0xffffffffu, p, 8);
            p += __shfl_xor_sync(0xffffffffu, p, 4);
            p += __shfl_xor_sync(0xffffffffu, p, 2);
            p += __shfl_xor_sync(0xffffffffu, p, 1);
            if (n == 0) {
                float zv = __half2float(sz[buf][s][cj]);
                float yv = (p + xcv * Dv) * siluf(zv);
                yh[(size_t)(lbase + s) * DI + e] = __float2half(yv);
            }
        }
        __syncthreads();
    }
}

// ======================= launch ==============================================
extern "C" void kernel_launch(void* const* d_in, const int* in_sizes, int n_in,
                              void* d_out, int out_size)
{
    const float* x_in  = (const float*)d_in[0];
    const float* ln_w  = (const float*)d_in[1];
    const float* ln_b  = (const float*)d_in[2];
    const float* inw   = (const float*)d_in[3];
    const float* cw    = (const float*)d_in[4];
    const float* cb    = (const float*)d_in[5];
    const float* xpw   = (const float*)d_in[6];
    const float* dtw   = (const float*)d_in[7];
    const float* dtb   = (const float*)d_in[8];
    const float* alog  = (const float*)d_in[9];
    const float* dskip = (const float*)d_in[10];
    const float* outw  = (const float*)d_in[11];
    const float* nfw   = (const float*)d_in[12];
    const float* nfb   = (const float*)d_in[13];
    float* out = (float*)d_out;

    float *px, *pdbl, *pdblp, *pdt;
    __half *phh, *pxz, *pxch, *pyh, *pdah;
    __half *winh, *wxph, *wxpl, *wdth, *wdtl, *woth;
    cudaGetSymbolAddress((void**)&px,   g_x);
    cudaGetSymbolAddress((void**)&pdbl, g_dbl);
    cudaGetSymbolAddress((void**)&pdblp,g_dblp);
    cudaGetSymbolAddress((void**)&pdt,  g_dt);
    cudaGetSymbolAddress((void**)&phh,  g_h_h);
    cudaGetSymbolAddress((void**)&pxz,  g_xz);
    cudaGetSymbolAddress((void**)&pxch, g_xc_h);
    cudaGetSymbolAddress((void**)&pyh,  g_y_h);
    cudaGetSymbolAddress((void**)&pdah, g_da_h);
    cudaGetSymbolAddress((void**)&winh, g_inw_h);
    cudaGetSymbolAddress((void**)&wxph, g_xpw_h);
    cudaGetSymbolAddress((void**)&wxpl, g_xpw_l);
    cudaGetSymbolAddress((void**)&wdth, g_dtw_h);
    cudaGetSymbolAddress((void**)&wdtl, g_dtw_l);
    cudaGetSymbolAddress((void**)&woth, g_otw_h);

    const int SMEM1 = 3 * 24576;  // NPASS1 3-stage
    const int SMEM2 = 2 * 40960;  // NPASS2 2-stage
    cudaFuncSetAttribute((const void*)gemm_mma<0,1,1>, cudaFuncAttributeMaxDynamicSharedMemorySize, SMEM1);
    cudaFuncSetAttribute((const void*)gemm_mma<0,2,0>, cudaFuncAttributeMaxDynamicSharedMemorySize, SMEM2);
    cudaFuncSetAttribute((const void*)gemm_mma<1,2,0>, cudaFuncAttributeMaxDynamicSharedMemorySize, SMEM2);
    cudaFuncSetAttribute((const void*)gemm_mma<2,1,0>, cudaFuncAttributeMaxDynamicSharedMemorySize, SMEM1);

    // weight converts
    { int n = 2 * 2 * DI * DM; convert_h_kernel<<<(n + 255) / 256, 256>>>(inw,  winh, n); }
    { int n = 2 * DBLC * DI;   convert_split_kernel<<<(n + 255) / 256, 256>>>(xpw, wxph, wxpl, n); }
    { int n = 2 * DI * DTR;    convert_split_kernel<<<(n + 255) / 256, 256>>>(dtw, wdth, wdtl, n); }
    { int n = 2 * DM * DI;     convert_h_kernel<<<(n + 255) / 256, 256>>>(outw, woth, n); }

    for (int i = 0; i < 2; i++) {
        // layernorm -> fp16 h (layer 0 reads harness input directly)
        ln_kernel<1><<<LSEQ, 256>>>(i == 0 ? x_in : px,
                                    ln_w + i * DM, ln_b + i * DM, nullptr, phh);

        // in_proj (1-pass fp16 -> fp16 out): [L,4096] = h @ inw^T (K=1024)
        gemm_mma<0,1,1><<<dim3(2 * DI / 128, LSEQ / 64), 128, SMEM1>>>(
            phh, winh + (size_t)i * 2 * DI * DM, nullptr,
            pxz, nullptr, 2 * DI, 2 * DI, DM, DM, nullptr, 0);

        // conv + silu (fp16 in/out)
        conv_silu_kernel<<<(LSEQ * DI + 255) / 256, 256>>>(
            pxz, cw + (size_t)i * DI * 4, cb + (size_t)i * DI, pxch);

        // x_proj split-K (2-pass, exact B): partials[z] over K-slice z
        gemm_mma<0,2,0><<<dim3(1, LSEQ / 64, XP_SPLITS), 128, SMEM2>>>(
            pxch, wxph + (size_t)i * DBLC * DI, wxpl + (size_t)i * DBLC * DI,
            pdblp, nullptr, DBLC, DBLC, DI, DI / XP_SPLITS, nullptr, LSEQ * DBLC);
        reduce_dbl_kernel<<<(LSEQ * DBLC + 255) / 256, 256>>>(pdblp, pdbl, pdah);

        // dt_proj + softplus (2-pass, exact B) -> fp32 dt: [L,2048] (K=64)
        gemm_mma<1,2,0><<<dim3(DI / 128, LSEQ / 64), 128, SMEM2>>>(
            pdah, wdth + (size_t)i * DI * DTR, wdtl + (size_t)i * DI * DTR,
            pdt, nullptr, DI, DI, DTR, DTR, dtb + (size_t)i * DI, 0);

        // selective scan -> fp16 y
        scan_kernel<<<DI / 16, 256>>>(
            pdbl, pdt, pxz, pxch,
            alog + (size_t)i * DI * DS, dskip + (size_t)i * DI, pyh);

        // out_proj + residual: px = res + y @ outw^T (res = x_in for layer 0)
        gemm_mma<2,1,0><<<dim3(DM / 128, LSEQ / 64), 128, SMEM1>>>(
            pyh, woth + (size_t)i * DM * DI, nullptr,
            px, (i == 0 ? x_in : px), DM, DM, DI, DI, nullptr, 0);
    }

    // final layernorm -> fp32 output
    ln_kernel<0><<<LSEQ, 256>>>(px, nfw, nfb, out, nullptr);
}

// round 17
// speedup vs baseline: 1.0135x; 1.0135x over previous
#include <cuda_runtime.h>
#include <cuda_fp16.h>
#include <math.h>
#include <stdint.h>

#define LSEQ 2048
#define DM   1024
#define DI   2048
#define DS   16
#define DTR  64
#define DBLC 96   /* DTR + 2*DS */
#define XP_SPLITS 8

// ======================= static scratch (no allocation) ======================
__device__ float g_x  [LSEQ * DM];        // residual stream (fp32)
__device__ float g_xz [LSEQ * 2 * DI];    // in_proj out [xc | z]
__device__ float g_xc [LSEQ * DI];        // conv+silu (fp32, for scan)
__device__ float g_dbl[LSEQ * DBLC];      // x_proj out
__device__ float g_dblp[XP_SPLITS * LSEQ * DBLC]; // split-K partials
__device__ float g_dt [LSEQ * DI];        // softplus(dt_proj)

// fp16 activation buffers (hi only)
__device__ __align__(16) __half g_h_h  [LSEQ * DM];
__device__ __align__(16) __half g_xc_h [LSEQ * DI];
__device__ __align__(16) __half g_y_h  [LSEQ * DI];
__device__ __align__(16) __half g_da_h [LSEQ * DTR];

// fp16 weights: hi for all; lo only for x_proj/dt_proj (2-pass, exact-B)
__device__ __align__(16) __half g_inw_h[2 * 2 * DI * DM];
__device__ __align__(16) __half g_xpw_h[2 * DBLC * DI];
__device__ __align__(16) __half g_xpw_l[2 * DBLC * DI];
__device__ __align__(16) __half g_dtw_h[2 * DI * DTR];
__device__ __align__(16) __half g_dtw_l[2 * DI * DTR];
__device__ __align__(16) __half g_otw_h[2 * DM * DI];

// ======================= helpers =============================================
__device__ __forceinline__ float siluf(float x) { return x / (1.0f + __expf(-x)); }
__device__ __forceinline__ float softplusf(float x) {
    if (x > 20.0f) return x;
    return log1pf(__expf(x));
}
__device__ __forceinline__ void split_fp16(float v, __half& h, __half& l) {
    h = __float2half(v);
    l = __float2half(v - __half2float(h));
}
__device__ __forceinline__ uint32_t smem_u32(const void* p) {
    uint32_t a;
    asm("{ .reg .u64 t; cvta.to.shared.u64 t, %1; cvt.u32.u64 %0, t; }" : "=r"(a) : "l"(p));
    return a;
}

__device__ __forceinline__ void cpa16(uint32_t d, const void* s, int sz) {
    asm volatile("cp.async.cg.shared.global [%0], [%1], 16, %2;" :: "r"(d), "l"(s), "r"(sz) : "memory");
}
__device__ __forceinline__ void cpa16f(uint32_t d, const void* s) {
    asm volatile("cp.async.cg.shared.global [%0], [%1], 16;" :: "r"(d), "l"(s) : "memory");
}
#define CP_COMMIT() asm volatile("cp.async.commit_group;" ::: "memory")
#define CP_WAIT(n)  asm volatile("cp.async.wait_group %0;" :: "n"(n) : "memory")

#define LDSM4(r0, r1, r2, r3, addr)                                            \
    asm volatile("ldmatrix.sync.aligned.m8n8.x4.shared.b16 {%0,%1,%2,%3}, [%4];" \
        : "=r"(r0), "=r"(r1), "=r"(r2), "=r"(r3) : "r"(addr))

#define MMA16816(d, a, b)                                                      \
    asm volatile("mma.sync.aligned.m16n8k16.row.col.f32.f16.f16.f32 "          \
        "{%0,%1,%2,%3},{%4,%5,%6,%7},{%8,%9},{%0,%1,%2,%3};"                   \
        : "+f"((d)[0]), "+f"((d)[1]), "+f"((d)[2]), "+f"((d)[3])               \
        : "r"((a)[0]), "r"((a)[1]), "r"((a)[2]), "r"((a)[3]),                  \
          "r"((b)[0]), "r"((b)[1]))

// ======================= HMMA GEMM ===========================================
// C[m,n] = sum_k A[m,k]*B[n,k], fp16. BK=64 (128B rows, slot^=(r&7) swizzle).
// NPASS=1: acc += Ah*Bh — 24KB stage, 3-stage ring, single sync/iter.
// NPASS=2: + Ah*Bl (exact-B) — 40KB stage, 2-stage, 2 syncs/iter (R14-proven).
// BM=64, BN=128, 128 threads, 4 warps (2m x 2n), warp tile 32x64.
// Occupancy in proven 2-4 CTAs/SM window (R12/R13 A/B).
// float2 epilogue. EPI 0: store; 1: softplus(+bias); 2: acc + res residual.
// Split-K via blockIdx.z (stores to C + z*czoff).

#define OFF_B   8192
#define OFF_BLO 24576

template<int NPASS>
__device__ __forceinline__ void stage_load(
    uint32_t sbase,
    const __half* __restrict__ Ah,
    const __half* __restrict__ Bh, const __half* __restrict__ Bl,
    int m0, int n0, int k0, int K, int Nmat, int tid)
{
    // A: 64 rows x 128B
    #pragma unroll
    for (int it = 0; it < 4; it++) {
        int id   = tid + it * 128;       // 0..511
        int r    = id >> 3;              // 0..63
        int slot = id & 7;
        uint32_t so = (uint32_t)(r * 128 + ((slot ^ (r & 7)) << 4));
        size_t ga = (size_t)(m0 + r) * K + k0 + slot * 8;
        cpa16(sbase + so, Ah + ga, 16);
    }
    // B: 128 rows x 128B (hi; lo only for NPASS==2)
    #pragma unroll
    for (int it = 0; it < 8; it++) {
        int id   = tid + it * 128;       // 0..1023
        int r    = id >> 3;              // 0..127
        int slot = id & 7;
        uint32_t so = (uint32_t)(r * 128 + ((slot ^ (r & 7)) << 4));
        int nrow = n0 + r;
        bool ok  = nrow < Nmat;
        size_t gb = (size_t)(ok ? nrow : 0) * K + k0 + slot * 8;
        cpa16(sbase + OFF_B + so, Bh + gb, ok ? 16 : 0);
        if (NPASS == 2) cpa16(sbase + OFF_BLO + so, Bl + gb, ok ? 16 : 0);
    }
}

template<int EPI, int NPASS>
__global__ void __launch_bounds__(128) gemm_mma(
    const __half* __restrict__ Ah,
    const __half* __restrict__ Bh, const __half* __restrict__ Bl,
    float* __restrict__ C, const float* __restrict__ res,
    int ldc, int Nmat, int K, int Kslice,
    const float* __restrict__ bias, int czoff)
{
    constexpr int SS = (NPASS == 1) ? 24576 : 40960;  // stage bytes
    constexpr int NS = (NPASS == 1) ? 3 : 2;          // ring depth

    extern __shared__ char smem[];
    const uint32_t sb = smem_u32(smem);
    const int tid  = threadIdx.x;
    const int lane = tid & 31;
    const int wid  = tid >> 5;
    const int m0   = blockIdx.y * 64;
    const int n0   = blockIdx.x * 128;
    const int kbase = blockIdx.z * Kslice;
    const int wm   = (wid & 1) * 32;    // warp m offset in tile
    const int wn   = (wid >> 1) * 64;   // warp n offset in tile

    // precompute ldmatrix lane offsets (ks=0); ks toggles ^(ks<<5)
    uint32_t aoff[2], boff[4];
    {
        int mat = lane >> 3, row = lane & 7;
        #pragma unroll
        for (int mf = 0; mf < 2; mf++) {
            int r = wm + mf * 16 + ((mat & 1) << 3) + row;
            int slot0 = mat >> 1;
            aoff[mf] = (uint32_t)(r * 128 + ((slot0 ^ (r & 7)) << 4));
        }
        #pragma unroll
        for (int p = 0; p < 4; p++) {
            int n = wn + p * 16 + ((mat >> 1) << 3) + row;
            int slot0 = mat & 1;
            boff[p] = (uint32_t)(n * 128 + ((slot0 ^ (n & 7)) << 4));
        }
    }

    float acc[2][8][4];
    #pragma unroll
    for (int i = 0; i < 2; i++)
        #pragma unroll
        for (int j = 0; j < 8; j++)
            #pragma unroll
            for (int q = 0; q < 4; q++) acc[i][j][q] = 0.f;

    const int nsteps = Kslice >> 6;

    if (NS == 3) {
        const int pre = (2 < nsteps) ? 2 : nsteps;
        for (int t = 0; t < pre; t++) {
            stage_load<NPASS>(sb + t * SS, Ah, Bh, Bl,
                              m0, n0, kbase + (t << 6), K, Nmat, tid);
            CP_COMMIT();
        }
    } else {
        stage_load<NPASS>(sb, Ah, Bh, Bl, m0, n0, kbase, K, Nmat, tid);
        CP_COMMIT();
    }

    for (int s = 0; s < nsteps; s++) {
        if (NS == 3) {
            if (s + 2 < nsteps) CP_WAIT(1);
            else                CP_WAIT(0);
            __syncthreads();
            if (s + 2 < nsteps) {
                stage_load<NPASS>(sb + ((s + 2) % 3) * SS, Ah, Bh, Bl,
                                  m0, n0, kbase + ((s + 2) << 6), K, Nmat, tid);
                CP_COMMIT();
            }
        } else {
            CP_WAIT(0);
            __syncthreads();
        }

        const uint32_t base = sb + (s % NS) * SS;
        #pragma unroll
        for (int ks = 0; ks < 4; ks++) {
            const uint32_t kx = (uint32_t)ks << 5;
            uint32_t ah[2][4], bh[8][2], bl[8][2];
            #pragma unroll
            for (int mf = 0; mf < 2; mf++)
                LDSM4(ah[mf][0], ah[mf][1], ah[mf][2], ah[mf][3], base + (aoff[mf] ^ kx));
            #pragma unroll
            for (int p = 0; p < 4; p++) {
                LDSM4(bh[2*p][0], bh[2*p][1], bh[2*p+1][0], bh[2*p+1][1],
                      base + OFF_B + (boff[p] ^ kx));
                if (NPASS == 2)
                    LDSM4(bl[2*p][0], bl[2*p][1], bl[2*p+1][0], bl[2*p+1][1],
                          base + OFF_BLO + (boff[p] ^ kx));
            }
            #pragma unroll
            for (int mf = 0; mf < 2; mf++)
                #pragma unroll
                for (int nf = 0; nf < 8; nf++)
                    MMA16816(acc[mf][nf], ah[mf], bh[nf]);
            if (NPASS == 2) {
                #pragma unroll
                for (int mf = 0; mf < 2; mf++)
                    #pragma unroll
                    for (int nf = 0; nf < 8; nf++)
                        MMA16816(acc[mf][nf], ah[mf], bl[nf]);
            }
        }

        if (NS == 2) {
            __syncthreads();
            if (s + 1 < nsteps) {
                stage_load<NPASS>(sb + ((s + 1) & 1) * SS, Ah, Bh, Bl,
                                  m0, n0, kbase + ((s + 1) << 6), K, Nmat, tid);
                CP_COMMIT();
            }
        }
    }

    // ---------------- epilogue (float2 vectorized) ----------------
    float* Cz = C + (size_t)blockIdx.z * czoff;
    const int mrow = m0 + wm + (lane >> 2);
    const int ncol = n0 + wn + (lane & 3) * 2;   // even; pairs (n, n+1)
    #pragma unroll
    for (int mf = 0; mf < 2; mf++) {
        #pragma unroll
        for (int nf = 0; nf < 8; nf++) {
            const int n = ncol + nf * 8;
            if (n < Nmat) {
                #pragma unroll
                for (int half = 0; half < 2; half++) {
                    const int m = mrow + mf * 16 + half * 8;
                    float2 v = make_float2(acc[mf][nf][half * 2 + 0],
                                           acc[mf][nf][half * 2 + 1]);
                    if (EPI == 1) {
                        v.x = softplusf(v.x + bias[n]);
                        v.y = softplusf(v.y + bias[n + 1]);
                    }
                    if (EPI == 2) {
                        float2 r = *(const float2*)(res + (size_t)m * ldc + n);
                        v.x += r.x; v.y += r.y;
                    }
                    *(float2*)(Cz + (size_t)m * ldc + n) = v;
                }
            }
        }
    }
}

// reduce split-K partials + extract dt_lr fp16 in one pass
__global__ void reduce_dbl_kernel(const float* __restrict__ p, float* __restrict__ d,
                                  __half* __restrict__ dah) {
    int i = blockIdx.x * blockDim.x + threadIdx.x;
    if (i >= LSEQ * DBLC) return;
    float s = 0.f;
    #pragma unroll
    for (int z = 0; z < XP_SPLITS; z++) s += p[z * LSEQ * DBLC + i];
    d[i] = s;
    int row = i / DBLC, c = i - row * DBLC;
    if (c < DTR) dah[row * DTR + c] = __float2half(s);
}

// ======================= merged weight convert ===============================
#define NW1 (2 * 2 * DI * DM)   // inw  (h only)
#define NW2 (2 * DBLC * DI)     // xpw  (h + l)
#define NW3 (2 * DI * DTR)      // dtw  (h + l)
#define NW4 (2 * DM * DI)       // outw (h only)
#define NW_TOTAL (NW1 + NW2 + NW3 + NW4)

__global__ void convert_weights_kernel(
    const float* __restrict__ inw,  __half* __restrict__ winh,
    const float* __restrict__ xpw,  __half* __restrict__ wxph, __half* __restrict__ wxpl,
    const float* __restrict__ dtw,  __half* __restrict__ wdth, __half* __restrict__ wdtl,
    const float* __restrict__ outw, __half* __restrict__ woth)
{
    int i = blockIdx.x * blockDim.x + threadIdx.x;
    if (i < NW1) { winh[i] = __float2half(inw[i]); return; }
    i -= NW1;
    if (i < NW2) {
        __half h, l; split_fp16(xpw[i], h, l);
        wxph[i] = h; wxpl[i] = l; return;
    }
    i -= NW2;
    if (i < NW3) {
        __half h, l; split_fp16(dtw[i], h, l);
        wdth[i] = h; wdtl[i] = l; return;
    }
    i -= NW3;
    if (i < NW4) woth[i] = __float2half(outw[i]);
}

// ======================= misc kernels ========================================
// layernorm -> fp16 hi (BF=1) or fp32 (BF=0)
template<int BF>
__global__ void __launch_bounds__(256) ln_kernel(
    const float* __restrict__ x, const float* __restrict__ w, const float* __restrict__ b,
    float* __restrict__ outf, __half* __restrict__ oh)
{
    int row = blockIdx.x, t = threadIdx.x;
    const float* xr = x + row * DM;
    float4 v = *(const float4*)(xr + t * 4);
    float s  = v.x + v.y + v.z + v.w;
    float ss = v.x * v.x + v.y * v.y + v.z * v.z + v.w * v.w;
    #pragma unroll
    for (int o = 16; o; o >>= 1) {
        s  += __shfl_xor_sync(0xffffffffu, s,  o);
        ss += __shfl_xor_sync(0xffffffffu, ss, o);
    }
    __shared__ float sr[8], sq[8], smu, srs;
    int wid = t >> 5, lane = t & 31;
    if (lane == 0) { sr[wid] = s; sq[wid] = ss; }
    __syncthreads();
    if (t == 0) {
        float S = 0.f, SS = 0.f;
        #pragma unroll
        for (int i = 0; i < 8; i++) { S += sr[i]; SS += sq[i]; }
        float mu = S * (1.0f / DM);
        smu = mu; srs = rsqrtf(SS * (1.0f / DM) - mu * mu + 1e-5f);
    }
    __syncthreads();
    float mu = smu, rs = srs;
    float4 wv = *(const float4*)(w + t * 4);
    float4 bv = *(const float4*)(b + t * 4);
    float o0 = (v.x - mu) * rs * wv.x + bv.x;
    float o1 = (v.y - mu) * rs * wv.y + bv.y;
    float o2 = (v.z - mu) * rs * wv.z + bv.z;
    float o3 = (v.w - mu) * rs * wv.w + bv.w;
    size_t base = (size_t)row * DM + t * 4;
    if (BF) {
        oh[base + 0] = __float2half(o0);
        oh[base + 1] = __float2half(o1);
        oh[base + 2] = __float2half(o2);
        oh[base + 3] = __float2half(o3);
    } else {
        float4 o4; o4.x = o0; o4.y = o1; o4.z = o2; o4.w = o3;
        *(float4*)(outf + base) = o4;
    }
}

// causal depthwise conv(k=4) + silu -> fp32 + fp16 hi
__global__ void conv_silu_kernel(const float* __restrict__ xz,
                                 const float* __restrict__ cw, const float* __restrict__ cb,
                                 float* __restrict__ xc, __half* __restrict__ xch)
{
    int idx = blockIdx.x * blockDim.x + threadIdx.x;
    if (idx >= LSEQ * DI) return;
    int l = idx / DI, e = idx - l * DI;
    float acc = cb[e];
    #pragma unroll
    for (int k = 0; k < 4; k++) {
        int ls = l + k - 3;
        if (ls >= 0) acc = fmaf(xz[(size_t)ls * (2 * DI) + e], cw[e * 4 + k], acc);
    }
    float v = siluf(acc);
    xc[idx] = v;
    xch[idx] = __float2half(v);
}

// ======= selective scan: smem-staged, cp.async double-buffered ===============
#define STT 64
#define NCHUNK (LSEQ / STT)

__global__ void __launch_bounds__(256) scan_kernel(
    const float* __restrict__ dbl, const float* __restrict__ dtf,
    const float* __restrict__ xz, const float* __restrict__ xc,
    const float* __restrict__ A_log, const float* __restrict__ Dp,
    __half* __restrict__ yh)
{
    __shared__ float sdt[2][STT][16];
    __shared__ float sxc[2][STT][16];
    __shared__ float sz [2][STT][16];
    __shared__ float sbc[2][STT][32];

    const int t  = threadIdx.x;
    const int n  = t & 15;          // state index
    const int cj = t >> 4;          // channel-in-block 0..15
    const int e0 = blockIdx.x * 16;
    const int e  = e0 + cj;

    const uint32_t a_dt = smem_u32(&sdt[0][0][0]);
    const uint32_t a_xc = smem_u32(&sxc[0][0][0]);
    const uint32_t a_z  = smem_u32(&sz [0][0][0]);
    const uint32_t a_bc = smem_u32(&sbc[0][0][0]);

    const float Aen = -__expf(A_log[e * DS + n]);
    const float Dv  = Dp[e];
    float h = 0.f;

    const int lr  = t >> 2, ls = t & 3;
    const int br  = t >> 3, bs = t & 7;

    auto load_chunk = [&](int c, int buf) {
        const int l0 = c * STT;
        const uint32_t bo = (uint32_t)buf * (STT * 16 * 4);
        const uint32_t bo2 = (uint32_t)buf * (STT * 32 * 4);
        cpa16f(a_dt + bo + (uint32_t)(lr * 64 + ls * 16),
               dtf + (size_t)(l0 + lr) * DI + e0 + ls * 4);
        cpa16f(a_xc + bo + (uint32_t)(lr * 64 + ls * 16),
               xc + (size_t)(l0 + lr) * DI + e0 + ls * 4);
        cpa16f(a_z + bo + (uint32_t)(lr * 64 + ls * 16),
               xz + (size_t)(l0 + lr) * (2 * DI) + DI + e0 + ls * 4);
        #pragma unroll
        for (int it = 0; it < 2; it++) {
            int row = br + it * 32;
            cpa16f(a_bc + bo2 + (uint32_t)(row * 128 + bs * 16),
                   dbl + (size_t)(l0 + row) * DBLC + DTR + bs * 4);
        }
    };

    load_chunk(0, 0);
    CP_COMMIT();

    for (int c = 0; c < NCHUNK; c++) {
        if (c + 1 < NCHUNK) {
            load_chunk(c + 1, (c + 1) & 1);
            CP_COMMIT();
            CP_WAIT(1);
        } else {
            CP_WAIT(0);
        }
        __syncthreads();

        const int buf = c & 1;
        const int lbase = c * STT;
        #pragma unroll 8
        for (int s = 0; s < STT; s++) {
            float dt  = sdt[buf][s][cj];
            float xcv = sxc[buf][s][cj];
            float Bv  = sbc[buf][s][n];
            float Cv  = sbc[buf][s][16 + n];
            float dA  = __expf(dt * Aen);
            h = fmaf(dA, h, dt * xcv * Bv);
            float p = h * Cv;
            p += __shfl_xor_sync(0xffffffffu, p, 8);
            p += __shfl_xor_sync(0xffffffffu, p, 4);
            p += __shfl_xor_sync(0xffffffffu, p, 2);
            p += __shfl_xor_sync(0xffffffffu, p, 1);
            if (n == 0) {
                float zv = sz[buf][s][cj];
                float yv = (p + xcv * Dv) * siluf(zv);
                yh[(size_t)(lbase + s) * DI + e] = __float2half(yv);
            }
        }
        __syncthreads();
    }
}

// ======================= launch ==============================================
extern "C" void kernel_launch(void* const* d_in, const int* in_sizes, int n_in,
                              void* d_out, int out_size)
{
    const float* x_in  = (const float*)d_in[0];
    const float* ln_w  = (const float*)d_in[1];
    const float* ln_b  = (const float*)d_in[2];
    const float* inw   = (const float*)d_in[3];
    const float* cw    = (const float*)d_in[4];
    const float* cb    = (const float*)d_in[5];
    const float* xpw   = (const float*)d_in[6];
    const float* dtw   = (const float*)d_in[7];
    const float* dtb   = (const float*)d_in[8];
    const float* alog  = (const float*)d_in[9];
    const float* dskip = (const float*)d_in[10];
    const float* outw  = (const float*)d_in[11];
    const float* nfw   = (const float*)d_in[12];
    const float* nfb   = (const float*)d_in[13];
    float* out = (float*)d_out;

    float *px, *pxz, *pxc, *pdbl, *pdblp, *pdt;
    __half *phh, *pxch, *pyh, *pdah;
    __half *winh, *wxph, *wxpl, *wdth, *wdtl, *woth;
    cudaGetSymbolAddress((void**)&px,   g_x);
    cudaGetSymbolAddress((void**)&pxz,  g_xz);
    cudaGetSymbolAddress((void**)&pxc,  g_xc);
    cudaGetSymbolAddress((void**)&pdbl, g_dbl);
    cudaGetSymbolAddress((void**)&pdblp,g_dblp);
    cudaGetSymbolAddress((void**)&pdt,  g_dt);
    cudaGetSymbolAddress((void**)&phh,  g_h_h);
    cudaGetSymbolAddress((void**)&pxch, g_xc_h);
    cudaGetSymbolAddress((void**)&pyh,  g_y_h);
    cudaGetSymbolAddress((void**)&pdah, g_da_h);
    cudaGetSymbolAddress((void**)&winh, g_inw_h);
    cudaGetSymbolAddress((void**)&wxph, g_xpw_h);
    cudaGetSymbolAddress((void**)&wxpl, g_xpw_l);
    cudaGetSymbolAddress((void**)&wdth, g_dtw_h);
    cudaGetSymbolAddress((void**)&wdtl, g_dtw_l);
    cudaGetSymbolAddress((void**)&woth, g_otw_h);

    const int SMEM1 = 3 * 24576;  // NPASS1 3-stage
    const int SMEM2 = 2 * 40960;  // NPASS2 2-stage
    cudaFuncSetAttribute((const void*)gemm_mma<0,1>, cudaFuncAttributeMaxDynamicSharedMemorySize, SMEM1);
    cudaFuncSetAttribute((const void*)gemm_mma<0,2>, cudaFuncAttributeMaxDynamicSharedMemorySize, SMEM2);
    cudaFuncSetAttribute((const void*)gemm_mma<1,2>, cudaFuncAttributeMaxDynamicSharedMemorySize, SMEM2);
    cudaFuncSetAttribute((const void*)gemm_mma<2,1>, cudaFuncAttributeMaxDynamicSharedMemorySize, SMEM1);

    // single merged weight convert
    convert_weights_kernel<<<(NW_TOTAL + 255) / 256, 256>>>(
        inw, winh, xpw, wxph, wxpl, dtw, wdth, wdtl, outw, woth);

    for (int i = 0; i < 2; i++) {
        // layernorm -> fp16 h (layer 0 reads harness input directly)
        ln_kernel<1><<<LSEQ, 256>>>(i == 0 ? x_in : px,
                                    ln_w + i * DM, ln_b + i * DM, nullptr, phh);

        // in_proj (1-pass fp16): [L,4096] = h @ inw^T (K=1024)
        gemm_mma<0,1><<<dim3(2 * DI / 128, LSEQ / 64), 128, SMEM1>>>(
            phh, winh + (size_t)i * 2 * DI * DM, nullptr,
            pxz, nullptr, 2 * DI, 2 * DI, DM, DM, nullptr, 0);

        // conv + silu
        conv_silu_kernel<<<(LSEQ * DI + 255) / 256, 256>>>(
            pxz, cw + (size_t)i * DI * 4, cb + (size_t)i * DI, pxc, pxch);

        // x_proj split-K (2-pass, exact B): partials[z] over K-slice z
        gemm_mma<0,2><<<dim3(1, LSEQ / 64, XP_SPLITS), 128, SMEM2>>>(
            pxch, wxph + (size_t)i * DBLC * DI, wxpl + (size_t)i * DBLC * DI,
            pdblp, nullptr, DBLC, DBLC, DI, DI / XP_SPLITS, nullptr, LSEQ * DBLC);
        reduce_dbl_kernel<<<(LSEQ * DBLC + 255) / 256, 256>>>(pdblp, pdbl, pdah);

        // dt_proj + softplus (2-pass, exact B): [L,2048] (K=64)
        gemm_mma<1,2><<<dim3(DI / 128, LSEQ / 64), 128, SMEM2>>>(
            pdah, wdth + (size_t)i * DI * DTR, wdtl + (size_t)i * DI * DTR,
            pdt, nullptr, DI, DI, DTR, DTR, dtb + (size_t)i * DI, 0);

        // selective scan -> fp16 y
        scan_kernel<<<DI / 16, 256>>>(
            pdbl, pdt, pxz, pxc,
            alog + (size_t)i * DI * DS, dskip + (size_t)i * DI, pyh);

        // out_proj + residual: px = res + y @ outw^T (res = x_in for layer 0)
        gemm_mma<2,1><<<dim3(DM / 128, LSEQ / 64), 128, SMEM1>>>(
            pyh, woth + (size_t)i * DM * DI, nullptr,
            px, (i == 0 ? x_in : px), DM, DM, DI, DI, nullptr, 0);
    }

    // final layernorm -> fp32 output
    ln_kernel<0><<<LSEQ, 256>>>(px, nfw, nfb, out, nullptr);
}